// round 14
// baseline (speedup 1.0000x reference)
#include <cuda_runtime.h>
#include <math.h>
#include <stdint.h>

// Problem constants
#define BATCH   32
#define NNODE   128
#define NIN     64
#define NHID    128
#define NOUT    64
#define NEDGE   16256            // N*(N-1)
#define M_ROWS  4096             // BATCH*NNODE
#define NBLK    128              // M_ROWS / BM (BM=32)

// ---------------- scratch (device globals; no allocation allowed) -----------
__device__ __align__(16) float g_h2[M_ROWS * NHID];
__device__ __align__(16) float g_y [M_ROWS * NHID];   // cols 0..63 ys(+bias), 64..127 yr
__device__ __align__(16) float g_w1t[NIN * NHID];     // [k=64][n=128]
__device__ __align__(16) float g_w2t[NHID * NHID];    // [k][n]
__device__ __align__(16) float g_woutt[NHID * NHID];  // [h][oc] oc<64: sender, oc>=64: recv
__device__ __align__(16) float g_bias[NHID];          // first 64 = folded bias, rest 0
__device__ __align__(16) float g_sa[NHID];            // BN scale per channel
__device__ __align__(16) float g_psum[NBLK * NHID];
__device__ __align__(16) float g_psq [NBLK * NHID];
__device__ unsigned g_ctr;
__device__ unsigned g_bctr[BATCH];   // per-batch y-ready arrivals

__device__ __forceinline__ float elu(float x) { return x > 0.f ? x : expm1f(x); }

__device__ __forceinline__ void cp16(void* dst, const void* src) {
    uint32_t d = (uint32_t)__cvta_generic_to_shared(dst);
    asm volatile("cp.async.cg.shared.global [%0], [%1], 16;" :: "r"(d), "l"(src) : "memory");
}
#define CP_COMMIT()  asm volatile("cp.async.commit_group;" ::: "memory")
#define CP_WAIT(n)   asm volatile("cp.async.wait_group %0;" :: "n"(n) : "memory")

// ---------------- K0: prep (weight transposes + counter resets) -------------
__global__ void prep_kernel(const float* __restrict__ W1,
                            const float* __restrict__ W2,
                            const float* __restrict__ Wout) {
    int t = blockIdx.x * blockDim.x + threadIdx.x;
    if (t == 0) g_ctr = 0u;
    if (t < BATCH) g_bctr[t] = 0u;
    if (t < 8192) {
        int f = t >> 7, h = t & 127;
        g_w1t[t] = W1[h * NIN + f];
    } else if (t < 24576) {
        int i = t - 8192;
        int k = i >> 7, n = i & 127;
        g_w2t[i] = W2[n * NHID + k];
    } else if (t < 40960) {
        int i = t - 24576;
        int h = i >> 7, oc = i & 127;
        g_woutt[i] = Wout[(oc & 63) * 256 + (oc >> 6) * 128 + h];
    }
}

// ---------------- K1: fused MLP, resident weights + last-block BN -----------
// dyn smem: W1s[64*128] | W2s[128*128] | h1s[32*128] | S[2048]  = 122880 B
__global__ __launch_bounds__(256) void mlp_fused_kernel(
    const float* __restrict__ X,     // [4096][64]
    const float* __restrict__ b1v,
    const float* __restrict__ b2v,
    const float* __restrict__ gamma,
    const float* __restrict__ beta,
    const float* __restrict__ Wout,
    const float* __restrict__ bout,
    float* __restrict__ H2,          // [4096][128]
    float* __restrict__ psum,
    float* __restrict__ psq)
{
    extern __shared__ float smem[];
    float* W1s = smem;               // 8192 floats
    float* W2s = smem + 8192;        // 16384 floats
    float* h1s = smem + 24576;       // 4096 floats
    float* S   = smem + 28672;       // 2048 floats (X tile / stats)
    __shared__ unsigned s_done;

    const int tid = threadIdx.x;
    const int tx  = tid & 31;
    const int ty  = tid >> 5;        // 0..7, 4 rows each
    const int row0 = blockIdx.x * 32;

    // Prefetch whole weights
    #pragma unroll
    for (int i = 0; i < 8; i++) {
        int f = tid + i * 256;
        cp16(&W1s[f * 4], &g_w1t[f * 4]);
    }
    CP_COMMIT();
    #pragma unroll
    for (int i = 0; i < 16; i++) {
        int f = tid + i * 256;
        cp16(&W2s[f * 4], &g_w2t[f * 4]);
    }
    CP_COMMIT();

    // X tile: 512 float4, 2 per thread
    #pragma unroll
    for (int i = 0; i < 2; i++) {
        int f = tid + i * 256;
        int m = f >> 4, kg = f & 15;
        *(float4*)&S[m * 64 + kg * 4] = *(const float4*)&X[(row0 + m) * 64 + kg * 4];
    }

    CP_WAIT(1);
    __syncthreads();

    // ---- GEMM1 ----
    float acc[4][4] = {};
    #pragma unroll 8
    for (int k = 0; k < NIN; k++) {
        float4 b4 = *(float4*)&W1s[k * 128 + tx * 4];
        #pragma unroll
        for (int i = 0; i < 4; i++) {
            float a = S[(ty * 4 + i) * 64 + k];
            acc[i][0] += a * b4.x;
            acc[i][1] += a * b4.y;
            acc[i][2] += a * b4.z;
            acc[i][3] += a * b4.w;
        }
    }
    {
        float4 bb = *(const float4*)&b1v[tx * 4];
        #pragma unroll
        for (int i = 0; i < 4; i++) {
            float4 o;
            o.x = elu(acc[i][0] + bb.x);
            o.y = elu(acc[i][1] + bb.y);
            o.z = elu(acc[i][2] + bb.z);
            o.w = elu(acc[i][3] + bb.w);
            *(float4*)&h1s[(ty * 4 + i) * 128 + tx * 4] = o;
        }
    }
    CP_WAIT(0);
    __syncthreads();

    // ---- GEMM2 ----
    float acc2[4][4] = {};
    #pragma unroll 8
    for (int k = 0; k < NHID; k++) {
        float4 b4 = *(float4*)&W2s[k * 128 + tx * 4];
        #pragma unroll
        for (int i = 0; i < 4; i++) {
            float a = h1s[(ty * 4 + i) * 128 + k];
            acc2[i][0] += a * b4.x;
            acc2[i][1] += a * b4.y;
            acc2[i][2] += a * b4.z;
            acc2[i][3] += a * b4.w;
        }
    }

    // Epilogue: ELU + bias + per-block channel stats + store h2
    float s[4]  = {0.f, 0.f, 0.f, 0.f};
    float s2[4] = {0.f, 0.f, 0.f, 0.f};
    {
        float4 bb = *(const float4*)&b2v[tx * 4];
        #pragma unroll
        for (int i = 0; i < 4; i++) {
            float4 o;
            o.x = elu(acc2[i][0] + bb.x);
            o.y = elu(acc2[i][1] + bb.y);
            o.z = elu(acc2[i][2] + bb.z);
            o.w = elu(acc2[i][3] + bb.w);
            s[0] += o.x; s2[0] += o.x * o.x;
            s[1] += o.y; s2[1] += o.y * o.y;
            s[2] += o.z; s2[2] += o.z * o.z;
            s[3] += o.w; s2[3] += o.w * o.w;
            *(float4*)&H2[(row0 + ty * 4 + i) * 128 + tx * 4] = o;
        }
    }
    __syncthreads();
    #pragma unroll
    for (int j = 0; j < 4; j++) {
        S[ty * 128 + tx * 4 + j]        = s[j];
        S[1024 + ty * 128 + tx * 4 + j] = s2[j];
    }
    __syncthreads();
    if (tid < 128) {
        float ps = 0.f, pq = 0.f;
        #pragma unroll
        for (int g = 0; g < 8; g++) {
            ps += S[g * 128 + tid];
            pq += S[1024 + g * 128 + tid];
        }
        psum[blockIdx.x * NHID + tid] = ps;
        psq [blockIdx.x * NHID + tid] = pq;
    }
    __threadfence();
    __syncthreads();
    if (tid == 0) {
        __threadfence();
        s_done = atomicAdd(&g_ctr, 1u);
    }
    __syncthreads();
    if (s_done != NBLK - 1) return;

    // ---- LAST BLOCK: global stats + BN fold scalars + folded bias ----
    float* ssum = S;
    float* ssq  = S + 1024;
    float* scf  = W1s;
    __syncthreads();
    {
        const int c4  = tid & 31;
        const int grp = tid >> 5;
        float4 A1 = make_float4(0.f, 0.f, 0.f, 0.f);
        float4 A2 = make_float4(0.f, 0.f, 0.f, 0.f);
        #pragma unroll
        for (int i = 0; i < 16; i++) {
            int blk = grp * 16 + i;
            float4 p = *(const float4*)&psum[blk * 128 + c4 * 4];
            float4 q = *(const float4*)&psq [blk * 128 + c4 * 4];
            A1.x += p.x; A1.y += p.y; A1.z += p.z; A1.w += p.w;
            A2.x += q.x; A2.y += q.y; A2.z += q.z; A2.w += q.w;
        }
        __syncthreads();
        *(float4*)&ssum[grp * 128 + c4 * 4] = A1;
        *(float4*)&ssq [grp * 128 + c4 * 4] = A2;
    }
    __syncthreads();
    if (tid < 128) {
        float ts = 0.f, tq = 0.f;
        #pragma unroll
        for (int g = 0; g < 8; g++) { ts += ssum[g * 128 + tid]; tq += ssq[g * 128 + tid]; }
        const float inv = 1.f / (float)M_ROWS;
        float mean = ts * inv;
        float var  = tq * inv - mean * mean;
        float a = gamma[tid] * rsqrtf(var + 1e-5f);
        float c = beta[tid] - a * mean;
        g_sa[tid] = a;
        scf[tid]  = c;
    }
    __syncthreads();
    {
        const int o  = tid >> 2;
        const int l4 = tid & 3;
        float bs = 0.f;
        #pragma unroll
        for (int i = 0; i < 16; i++) {
            float4 w = *(const float4*)&Wout[o * 256 + l4 * 64 + i * 4];
            int j0 = (l4 & 1) * 64 + i * 4;
            bs += w.x * scf[j0] + w.y * scf[j0 + 1] + w.z * scf[j0 + 2] + w.w * scf[j0 + 3];
        }
        bs += __shfl_down_sync(0xffffffffu, bs, 2, 4);
        bs += __shfl_down_sync(0xffffffffu, bs, 1, 4);
        if (l4 == 0) g_bias[o] = bs + bout[o];
        if (tid >= 64 && tid < 128) g_bias[tid] = 0.f;
    }
}

// ---------------- K2: gemm3 (own 16 rows, no duplication) + edge writes -----
// Block (b,g): phase A computes y rows rowb+g*16 .. +15 -> g_y; per-batch
// counter; phase B spins until the batch's 8 blocks arrive; phase C = round-6
// edge writer verbatim. Edge e: recv=e/127, i=e%127, send=i+(i>=recv).
__global__ __launch_bounds__(512, 2) void gemm_edge_kernel(
    const float* __restrict__ H2, float* __restrict__ out)
{
    __shared__ float As[16 * 128];       // 8KB sa-scaled h2 rows
    __shared__ float Bs[64 * 128];       // 32KB woutt k-tile
    __shared__ float sa_sh[128];
    __shared__ float bias_sh[128];
    __shared__ float yr_sh[16 * 64];     // 4KB

    const int tid  = threadIdx.x;
    const int b    = blockIdx.x >> 3;
    const int g    = blockIdx.x & 7;
    const int rowb = b << 7;
    const int r0   = g * 16;
    const int row0 = rowb + r0;

    if (tid < 128) { sa_sh[tid] = g_sa[tid]; bias_sh[tid] = g_bias[tid]; }
    __syncthreads();

    // As: 16 rows x 128 k, sa-scaled; 512 float4, 1 per thread
    {
        int m = tid >> 5, kg = tid & 31;
        float4 v  = *(const float4*)&H2[(row0 + m) * 128 + kg * 4];
        float4 sc = *(const float4*)&sa_sh[kg * 4];
        v.x *= sc.x; v.y *= sc.y; v.z *= sc.z; v.w *= sc.w;
        *(float4*)&As[m * 128 + kg * 4] = v;
    }

    const int tx = tid & 31;             // 4 cols
    const int ty = tid >> 5;             // 0..15, one row each
    float acc[4] = {0.f, 0.f, 0.f, 0.f};

    for (int kb = 0; kb < NHID; kb += 64) {
        __syncthreads();
        #pragma unroll
        for (int i = 0; i < 4; i++) {    // 2048 float4 / 512 thr
            int f = tid + i * 512;
            int k = f >> 5, ng = f & 31;
            *(float4*)&Bs[k * 128 + ng * 4] = *(const float4*)&g_woutt[(kb + k) * 128 + ng * 4];
        }
        __syncthreads();
        #pragma unroll
        for (int k = 0; k < 64; k++) {
            float4 b4 = *(float4*)&Bs[k * 128 + tx * 4];
            float  a  = As[ty * 128 + kb + k];     // warp-broadcast (ty const/warp)
            acc[0] += a * b4.x;
            acc[1] += a * b4.y;
            acc[2] += a * b4.z;
            acc[3] += a * b4.w;
        }
    }
    {
        float4 bb = *(const float4*)&bias_sh[tx * 4];  // upper half zeros
        float4 o;
        o.x = acc[0] + bb.x;
        o.y = acc[1] + bb.y;
        o.z = acc[2] + bb.z;
        o.w = acc[3] + bb.w;
        *(float4*)&g_y[(row0 + ty) * 128 + tx * 4] = o;
    }
    __threadfence();
    __syncthreads();
    if (tid == 0) {
        atomicAdd(&g_bctr[b], 1u);
        while (atomicAdd(&g_bctr[b], 0u) < 8u) __nanosleep(32);
        __threadfence();
    }
    __syncthreads();

    // ---- phase C: round-6 edge writer ----
    if (tid < 256) {
        int node = tid >> 4, q = tid & 15;
        *(float4*)&yr_sh[node * 64 + q * 4] =
            *(const float4*)&g_y[(rowb + r0 + node) * 128 + 64 + q * 4];
    }

    const int q  = tid & 15;
    const int sg = tid >> 4;             // senders sg*4 .. +3
    float4 ys4[4];
    #pragma unroll
    for (int j = 0; j < 4; j++)
        ys4[j] = __ldg((const float4*)&g_y[(rowb + sg * 4 + j) * 128 + q * 4]);

    __syncthreads();

    float4* outv = (float4*)out;
    const long base_b = (long)b * NEDGE;

    #pragma unroll 1
    for (int rl = 0; rl < 16; rl++) {
        const int rg = r0 + rl;
        float4 yr4 = *(float4*)&yr_sh[rl * 64 + q * 4];
        const long base = (base_b + (long)rg * 127) * 16 + q;
        #pragma unroll
        for (int j = 0; j < 4; j++) {
            int s = sg * 4 + j;
            if (s == rg) continue;       // no self-loop
            int i = s - (s > rg);
            float4 o;
            o.x = ys4[j].x + yr4.x;
            o.y = ys4[j].y + yr4.y;
            o.z = ys4[j].z + yr4.z;
            o.w = ys4[j].w + yr4.w;
            __stcs(&outv[base + (long)i * 16], o);
        }
    }
}

// ---------------- launcher ---------------------------------------------------
extern "C" void kernel_launch(void* const* d_in, const int* in_sizes, int n_in,
                              void* d_out, int out_size) {
    const float* x       = (const float*)d_in[0];
    const float* W1      = (const float*)d_in[3];
    const float* b1      = (const float*)d_in[4];
    const float* W2      = (const float*)d_in[5];
    const float* b2      = (const float*)d_in[6];
    const float* gamma   = (const float*)d_in[7];
    const float* beta    = (const float*)d_in[8];
    const float* Wout    = (const float*)d_in[9];
    const float* bout    = (const float*)d_in[10];
    float* out = (float*)d_out;

    float *p_h2, *p_psum, *p_psq;
    cudaGetSymbolAddress((void**)&p_h2,   g_h2);
    cudaGetSymbolAddress((void**)&p_psum, g_psum);
    cudaGetSymbolAddress((void**)&p_psq,  g_psq);

    static int attr_set = 0;
    if (!attr_set) {
        cudaFuncSetAttribute(mlp_fused_kernel,
                             cudaFuncAttributeMaxDynamicSharedMemorySize, 122880);
        attr_set = 1;
    }

    // prep: weight transposes + counter resets
    prep_kernel<<<40, 1024>>>(W1, W2, Wout);

    // fused MLP with resident weights + last-block BN
    mlp_fused_kernel<<<NBLK, 256, 122880>>>(x, b1, b2, gamma, beta, Wout, bout,
                                            p_h2, p_psum, p_psq);

    // gemm3 (1x work, per-batch flags) + edge writes in one kernel
    gemm_edge_kernel<<<256, 512>>>(p_h2, out);
}

// round 15
// speedup vs baseline: 1.0769x; 1.0769x over previous
#include <cuda_runtime.h>
#include <math.h>
#include <stdint.h>

// Problem constants
#define BATCH   32
#define NNODE   128
#define NIN     64
#define NHID    128
#define NOUT    64
#define NEDGE   16256            // N*(N-1)
#define M_ROWS  4096             // BATCH*NNODE
#define NBLK    128              // M_ROWS / BM (BM=32)

// ---------------- scratch (device globals; no allocation allowed) -----------
__device__ __align__(16) float g_h2[M_ROWS * NHID];
__device__ __align__(16) float g_y [M_ROWS * NHID];   // cols 0..63 ys(+bias), 64..127 yr
__device__ __align__(16) float g_w1t[NIN * NHID];     // [k=64][n=128]
__device__ __align__(16) float g_w2t[NHID * NHID];    // [k][n]
__device__ __align__(16) float g_woutt[NHID * NHID];  // [h][oc] oc<64: sender, oc>=64: recv
__device__ __align__(16) float g_bias[NHID];          // first 64 = folded bias, rest 0
__device__ __align__(16) float g_sa[NHID];            // BN scale per channel
__device__ __align__(16) float g_psum[NBLK * NHID];
__device__ __align__(16) float g_psq [NBLK * NHID];
__device__ unsigned g_ctr;

__device__ __forceinline__ float elu(float x) { return x > 0.f ? x : expm1f(x); }

__device__ __forceinline__ void cp16(void* dst, const void* src) {
    uint32_t d = (uint32_t)__cvta_generic_to_shared(dst);
    asm volatile("cp.async.cg.shared.global [%0], [%1], 16;" :: "r"(d), "l"(src) : "memory");
}
#define CP_COMMIT()  asm volatile("cp.async.commit_group;" ::: "memory")
#define CP_WAIT(n)   asm volatile("cp.async.wait_group %0;" :: "n"(n) : "memory")

// ---------------- K0: prep — coalesced reads, scattered writes --------------
// 10240 float4 total: [0,2048) W1, [2048,6144) W2, [6144,10240) Wout.
__global__ void prep_kernel(const float* __restrict__ W1,
                            const float* __restrict__ W2,
                            const float* __restrict__ Wout) {
    int t = blockIdx.x * blockDim.x + threadIdx.x;
    if (t == 0) g_ctr = 0u;
    if (t < 2048) {
        // W1 [128][64]: read linear float4, write w1t[f][h]
        float4 v = *(const float4*)&W1[t * 4];
        int h = t >> 4, f0 = (t & 15) * 4;
        g_w1t[(f0 + 0) * 128 + h] = v.x;
        g_w1t[(f0 + 1) * 128 + h] = v.y;
        g_w1t[(f0 + 2) * 128 + h] = v.z;
        g_w1t[(f0 + 3) * 128 + h] = v.w;
    } else if (t < 6144) {
        int i = t - 2048;            // W2 [128][128]: w2t[k][n]
        float4 v = *(const float4*)&W2[i * 4];
        int n = i >> 5, k0 = (i & 31) * 4;
        g_w2t[(k0 + 0) * 128 + n] = v.x;
        g_w2t[(k0 + 1) * 128 + n] = v.y;
        g_w2t[(k0 + 2) * 128 + n] = v.z;
        g_w2t[(k0 + 3) * 128 + n] = v.w;
    } else if (t < 10240) {
        int i = t - 6144;            // Wout [64][256]: woutt[h][half*64+o]
        float4 v = *(const float4*)&Wout[i * 4];
        int o = i >> 6, c0 = (i & 63) * 4;
        const float vv[4] = {v.x, v.y, v.z, v.w};
        #pragma unroll
        for (int j = 0; j < 4; j++) {
            int c = c0 + j;
            g_woutt[(c & 127) * 128 + (c >> 7) * 64 + o] = vv[j];
        }
    }
}

// ---------------- K1: fused MLP, resident weights + last-block BN -----------
// dyn smem: W1s[64*128] | W2s[128*128] | h1s[32*128] | S[2048]  = 122880 B
__global__ __launch_bounds__(256) void mlp_fused_kernel(
    const float* __restrict__ X,     // [4096][64]
    const float* __restrict__ b1v,
    const float* __restrict__ b2v,
    const float* __restrict__ gamma,
    const float* __restrict__ beta,
    const float* __restrict__ Wout,
    const float* __restrict__ bout,
    float* __restrict__ H2,          // [4096][128]
    float* __restrict__ psum,
    float* __restrict__ psq)
{
    extern __shared__ float smem[];
    float* W1s = smem;               // 8192 floats
    float* W2s = smem + 8192;        // 16384 floats
    float* h1s = smem + 24576;       // 4096 floats
    float* S   = smem + 28672;       // 2048 floats (X tile / stats)
    __shared__ unsigned s_done;

    const int tid = threadIdx.x;
    const int tx  = tid & 31;
    const int ty  = tid >> 5;        // 0..7, 4 rows each
    const int row0 = blockIdx.x * 32;

    // Prefetch whole weights
    #pragma unroll
    for (int i = 0; i < 8; i++) {
        int f = tid + i * 256;
        cp16(&W1s[f * 4], &g_w1t[f * 4]);
    }
    CP_COMMIT();
    #pragma unroll
    for (int i = 0; i < 16; i++) {
        int f = tid + i * 256;
        cp16(&W2s[f * 4], &g_w2t[f * 4]);
    }
    CP_COMMIT();

    // X tile: 512 float4, 2 per thread
    #pragma unroll
    for (int i = 0; i < 2; i++) {
        int f = tid + i * 256;
        int m = f >> 4, kg = f & 15;
        *(float4*)&S[m * 64 + kg * 4] = *(const float4*)&X[(row0 + m) * 64 + kg * 4];
    }

    CP_WAIT(1);
    __syncthreads();

    // ---- GEMM1: k chunks of 4, vectorized a-broadcasts ----
    float acc[4][4] = {};
    #pragma unroll 4
    for (int k0 = 0; k0 < NIN; k0 += 4) {
        float4 a4[4];
        #pragma unroll
        for (int i = 0; i < 4; i++)
            a4[i] = *(float4*)&S[(ty * 4 + i) * 64 + k0];
        #pragma unroll
        for (int kk = 0; kk < 4; kk++) {
            float4 b4 = *(float4*)&W1s[(k0 + kk) * 128 + tx * 4];
            #pragma unroll
            for (int i = 0; i < 4; i++) {
                float a = (&a4[i].x)[kk];
                acc[i][0] += a * b4.x;
                acc[i][1] += a * b4.y;
                acc[i][2] += a * b4.z;
                acc[i][3] += a * b4.w;
            }
        }
    }
    {
        float4 bb = *(const float4*)&b1v[tx * 4];
        #pragma unroll
        for (int i = 0; i < 4; i++) {
            float4 o;
            o.x = elu(acc[i][0] + bb.x);
            o.y = elu(acc[i][1] + bb.y);
            o.z = elu(acc[i][2] + bb.z);
            o.w = elu(acc[i][3] + bb.w);
            *(float4*)&h1s[(ty * 4 + i) * 128 + tx * 4] = o;
        }
    }
    CP_WAIT(0);
    __syncthreads();

    // ---- GEMM2: k chunks of 4 ----
    float acc2[4][4] = {};
    #pragma unroll 4
    for (int k0 = 0; k0 < NHID; k0 += 4) {
        float4 a4[4];
        #pragma unroll
        for (int i = 0; i < 4; i++)
            a4[i] = *(float4*)&h1s[(ty * 4 + i) * 128 + k0];
        #pragma unroll
        for (int kk = 0; kk < 4; kk++) {
            float4 b4 = *(float4*)&W2s[(k0 + kk) * 128 + tx * 4];
            #pragma unroll
            for (int i = 0; i < 4; i++) {
                float a = (&a4[i].x)[kk];
                acc2[i][0] += a * b4.x;
                acc2[i][1] += a * b4.y;
                acc2[i][2] += a * b4.z;
                acc2[i][3] += a * b4.w;
            }
        }
    }

    // Epilogue: ELU + bias + per-block channel stats + store h2
    float s[4]  = {0.f, 0.f, 0.f, 0.f};
    float s2[4] = {0.f, 0.f, 0.f, 0.f};
    {
        float4 bb = *(const float4*)&b2v[tx * 4];
        #pragma unroll
        for (int i = 0; i < 4; i++) {
            float4 o;
            o.x = elu(acc2[i][0] + bb.x);
            o.y = elu(acc2[i][1] + bb.y);
            o.z = elu(acc2[i][2] + bb.z);
            o.w = elu(acc2[i][3] + bb.w);
            s[0] += o.x; s2[0] += o.x * o.x;
            s[1] += o.y; s2[1] += o.y * o.y;
            s[2] += o.z; s2[2] += o.z * o.z;
            s[3] += o.w; s2[3] += o.w * o.w;
            *(float4*)&H2[(row0 + ty * 4 + i) * 128 + tx * 4] = o;
        }
    }
    __syncthreads();
    #pragma unroll
    for (int j = 0; j < 4; j++) {
        S[ty * 128 + tx * 4 + j]        = s[j];
        S[1024 + ty * 128 + tx * 4 + j] = s2[j];
    }
    __syncthreads();
    if (tid < 128) {
        float ps = 0.f, pq = 0.f;
        #pragma unroll
        for (int g = 0; g < 8; g++) {
            ps += S[g * 128 + tid];
            pq += S[1024 + g * 128 + tid];
        }
        psum[blockIdx.x * NHID + tid] = ps;
        psq [blockIdx.x * NHID + tid] = pq;
    }
    __threadfence();
    __syncthreads();
    if (tid == 0) {
        __threadfence();
        s_done = atomicAdd(&g_ctr, 1u);
    }
    __syncthreads();
    if (s_done != NBLK - 1) return;

    // ---- LAST BLOCK: global stats + BN fold scalars + folded bias ----
    float* ssum = S;
    float* ssq  = S + 1024;
    float* scf  = W1s;
    __syncthreads();
    {
        const int c4  = tid & 31;
        const int grp = tid >> 5;
        float4 A1 = make_float4(0.f, 0.f, 0.f, 0.f);
        float4 A2 = make_float4(0.f, 0.f, 0.f, 0.f);
        #pragma unroll
        for (int i = 0; i < 16; i++) {
            int blk = grp * 16 + i;
            float4 p = *(const float4*)&psum[blk * 128 + c4 * 4];
            float4 q = *(const float4*)&psq [blk * 128 + c4 * 4];
            A1.x += p.x; A1.y += p.y; A1.z += p.z; A1.w += p.w;
            A2.x += q.x; A2.y += q.y; A2.z += q.z; A2.w += q.w;
        }
        __syncthreads();
        *(float4*)&ssum[grp * 128 + c4 * 4] = A1;
        *(float4*)&ssq [grp * 128 + c4 * 4] = A2;
    }
    __syncthreads();
    if (tid < 128) {
        float ts = 0.f, tq = 0.f;
        #pragma unroll
        for (int g = 0; g < 8; g++) { ts += ssum[g * 128 + tid]; tq += ssq[g * 128 + tid]; }
        const float inv = 1.f / (float)M_ROWS;
        float mean = ts * inv;
        float var  = tq * inv - mean * mean;
        float a = gamma[tid] * rsqrtf(var + 1e-5f);
        float c = beta[tid] - a * mean;
        g_sa[tid] = a;
        scf[tid]  = c;
    }
    __syncthreads();
    {
        const int o  = tid >> 2;
        const int l4 = tid & 3;
        float bs = 0.f;
        #pragma unroll
        for (int i = 0; i < 16; i++) {
            float4 w = *(const float4*)&Wout[o * 256 + l4 * 64 + i * 4];
            int j0 = (l4 & 1) * 64 + i * 4;
            bs += w.x * scf[j0] + w.y * scf[j0 + 1] + w.z * scf[j0 + 2] + w.w * scf[j0 + 3];
        }
        bs += __shfl_down_sync(0xffffffffu, bs, 2, 4);
        bs += __shfl_down_sync(0xffffffffu, bs, 1, 4);
        if (l4 == 0) g_bias[o] = bs + bout[o];
        if (tid >= 64 && tid < 128) g_bias[tid] = 0.f;
    }
}

// ---------------- K2: GEMM3 y = h2 @ (sa*Wout)T + bias, resident B ----------
// dyn smem: Ws[128*128] | As[32*128]  = 81920 B
__global__ __launch_bounds__(256) void gemm3_kernel(const float* __restrict__ A,
                                                    float* __restrict__ C) {
    extern __shared__ float smem[];
    float* Ws = smem;                // 16384 floats
    float* As = smem + 16384;        // 4096 floats
    __shared__ float sa_sh[128];
    __shared__ float bias_sh[128];

    const int tid = threadIdx.x;
    const int tx  = tid & 31;
    const int ty  = tid >> 5;
    const int row0 = blockIdx.x * 32;

    #pragma unroll
    for (int i = 0; i < 16; i++) {
        int f = tid + i * 256;
        cp16(&Ws[f * 4], &g_woutt[f * 4]);
    }
    #pragma unroll
    for (int i = 0; i < 4; i++) {
        int f = tid + i * 256;
        cp16(&As[f * 4], &A[row0 * 128 + f * 4]);
    }
    CP_COMMIT();
    if (tid < 128) { sa_sh[tid] = g_sa[tid]; bias_sh[tid] = g_bias[tid]; }
    CP_WAIT(0);
    __syncthreads();

    // fold sa into B rows once: Ws[k][oc] *= sa[k]
    #pragma unroll
    for (int i = 0; i < 16; i++) {
        int f = tid + i * 256;
        int k = f >> 5;
        float4 v = *(float4*)&Ws[f * 4];
        float sc = sa_sh[k];
        v.x *= sc; v.y *= sc; v.z *= sc; v.w *= sc;
        *(float4*)&Ws[f * 4] = v;
    }
    __syncthreads();

    float acc[4][4] = {};
    #pragma unroll 4
    for (int k0 = 0; k0 < NHID; k0 += 4) {
        float4 a4[4];
        #pragma unroll
        for (int i = 0; i < 4; i++)
            a4[i] = *(float4*)&As[(ty * 4 + i) * 128 + k0];
        #pragma unroll
        for (int kk = 0; kk < 4; kk++) {
            float4 b4 = *(float4*)&Ws[(k0 + kk) * 128 + tx * 4];
            #pragma unroll
            for (int i = 0; i < 4; i++) {
                float a = (&a4[i].x)[kk];
                acc[i][0] += a * b4.x;
                acc[i][1] += a * b4.y;
                acc[i][2] += a * b4.z;
                acc[i][3] += a * b4.w;
            }
        }
    }

    float4 bb = *(const float4*)&bias_sh[tx * 4];
    #pragma unroll
    for (int i = 0; i < 4; i++) {
        float4 o;
        o.x = acc[i][0] + bb.x;
        o.y = acc[i][1] + bb.y;
        o.z = acc[i][2] + bb.z;
        o.w = acc[i][3] + bb.w;
        *(float4*)&C[(row0 + ty * 4 + i) * 128 + tx * 4] = o;
    }
}

// ---------------- K3: edge writer (round-6 best) ----------------------------
// Edge e: recv = e/127, i = e%127, send = i + (i >= recv).
__global__ __launch_bounds__(512) void edge_out_kernel(float* __restrict__ out) {
    __shared__ float yr_sh[16 * 64];     // 4KB

    const int tid = threadIdx.x;
    const int b   = blockIdx.x >> 3;
    const int r0  = (blockIdx.x & 7) * 16;
    const int rowb = b << 7;

    if (tid < 256) {
        int node = tid >> 4, q = tid & 15;
        *(float4*)&yr_sh[node * 64 + q * 4] =
            *(const float4*)&g_y[(rowb + r0 + node) * 128 + 64 + q * 4];
    }

    const int q  = tid & 15;
    const int sg = tid >> 4;             // senders sg*4 .. +3
    float4 ys4[4];
    #pragma unroll
    for (int j = 0; j < 4; j++)
        ys4[j] = __ldg((const float4*)&g_y[(rowb + sg * 4 + j) * 128 + q * 4]);

    __syncthreads();

    float4* outv = (float4*)out;
    const long base_b = (long)b * NEDGE;

    #pragma unroll 1
    for (int rl = 0; rl < 16; rl++) {
        const int rg = r0 + rl;
        float4 yr4 = *(float4*)&yr_sh[rl * 64 + q * 4];
        const long base = (base_b + (long)rg * 127) * 16 + q;
        #pragma unroll
        for (int j = 0; j < 4; j++) {
            int s = sg * 4 + j;
            if (s == rg) continue;       // no self-loop
            int i = s - (s > rg);
            float4 o;
            o.x = ys4[j].x + yr4.x;
            o.y = ys4[j].y + yr4.y;
            o.z = ys4[j].z + yr4.z;
            o.w = ys4[j].w + yr4.w;
            __stcs(&outv[base + (long)i * 16], o);
        }
    }
}

// ---------------- launcher ---------------------------------------------------
extern "C" void kernel_launch(void* const* d_in, const int* in_sizes, int n_in,
                              void* d_out, int out_size) {
    const float* x       = (const float*)d_in[0];
    const float* W1      = (const float*)d_in[3];
    const float* b1      = (const float*)d_in[4];
    const float* W2      = (const float*)d_in[5];
    const float* b2      = (const float*)d_in[6];
    const float* gamma   = (const float*)d_in[7];
    const float* beta    = (const float*)d_in[8];
    const float* Wout    = (const float*)d_in[9];
    const float* bout    = (const float*)d_in[10];
    float* out = (float*)d_out;

    float *p_h2, *p_y, *p_psum, *p_psq;
    cudaGetSymbolAddress((void**)&p_h2,   g_h2);
    cudaGetSymbolAddress((void**)&p_y,    g_y);
    cudaGetSymbolAddress((void**)&p_psum, g_psum);
    cudaGetSymbolAddress((void**)&p_psq,  g_psq);

    static int attr_set = 0;
    if (!attr_set) {
        cudaFuncSetAttribute(mlp_fused_kernel,
                             cudaFuncAttributeMaxDynamicSharedMemorySize, 122880);
        cudaFuncSetAttribute(gemm3_kernel,
                             cudaFuncAttributeMaxDynamicSharedMemorySize, 81920);
        attr_set = 1;
    }

    // prep: coalesced-read transposes + counter reset
    prep_kernel<<<10, 1024>>>(W1, W2, Wout);

    // fused MLP with resident weights + last-block BN
    mlp_fused_kernel<<<NBLK, 256, 122880>>>(x, b1, b2, gamma, beta, Wout, bout,
                                            p_h2, p_psum, p_psq);

    // GEMM3 with resident sa-folded Wout
    gemm3_kernel<<<NBLK, 256, 81920>>>(p_h2, p_y);

    // edge output (write-floor bound)
    edge_out_kernel<<<256, 512>>>(out);
}